// round 17
// baseline (speedup 1.0000x reference)
#include <cuda_runtime.h>
#include <cuda_fp16.h>
#include <cstdint>

// Problem constants
constexpr int B  = 2;
constexpr int S  = 2048;
constexpr int D  = 512;
constexpr int H  = 8;
constexpr int DK = 64;           // D / H

// Scratch (allocation-free rule: __device__ globals)
__device__ __half   g_qh[B * S * D];     // fp16 inputs
__device__ __half   g_kh[B * S * D];
__device__ __half   g_vh[B * S * D];
__device__ __half   g_wq[D * D];
__device__ __half   g_wo[D * D];
__device__ uint32_t g_Mb[S * S / 32];    // bit-packed mask, [row][S/32]
__device__ __half   g_Q[B * H * S * DK]; // [B,H,S,DK], pre-scaled by 1/8
__device__ __half   g_K[B * H * S * DK]; // [B,H,S,DK]
__device__ __half   g_V[B * H * DK * S]; // TRANSPOSED: [B,H,DK,S]
__device__ __half   g_X[B * S * D];      // attention output, [B,S,D]

// ---------------------------------------------------------------------------
// Helpers
// ---------------------------------------------------------------------------

__device__ __forceinline__ uint32_t pack2(float a, float b) {
    __half2 h = __floats2half2_rn(a, b);
    return *reinterpret_cast<uint32_t*>(&h);
}
__device__ __forceinline__ uint2 pack4(float4 f) {
    return make_uint2(pack2(f.x, f.y), pack2(f.z, f.w));
}
__device__ __forceinline__ uint32_t smem_u32(const void* p) {
    return (uint32_t)__cvta_generic_to_shared(p);
}

__device__ __forceinline__ void mma_f16(float4& c,
    uint32_t a0, uint32_t a1, uint32_t a2, uint32_t a3,
    uint32_t b0, uint32_t b1)
{
    asm volatile(
        "mma.sync.aligned.m16n8k16.row.col.f32.f16.f16.f32 "
        "{%0,%1,%2,%3},{%4,%5,%6,%7},{%8,%9},{%0,%1,%2,%3};"
        : "+f"(c.x), "+f"(c.y), "+f"(c.z), "+f"(c.w)
        : "r"(a0), "r"(a1), "r"(a2), "r"(a3), "r"(b0), "r"(b1));
}

__device__ __forceinline__ void ldsm4(uint32_t& d0, uint32_t& d1,
                                      uint32_t& d2, uint32_t& d3, uint32_t a)
{
    asm volatile(
        "ldmatrix.sync.aligned.m8n8.x4.shared.b16 {%0,%1,%2,%3},[%4];"
        : "=r"(d0), "=r"(d1), "=r"(d2), "=r"(d3) : "r"(a));
}

__device__ __forceinline__ void cp16(void* smem, const void* gmem) {
    asm volatile("cp.async.cg.shared.global [%0], [%1], 16;"
                 :: "r"(smem_u32(smem)), "l"(gmem));
}
__device__ __forceinline__ void cp_commit() {
    asm volatile("cp.async.commit_group;" ::: "memory");
}
template <int N>
__device__ __forceinline__ void cp_wait() {
    asm volatile("cp.async.wait_group %0;" :: "n"(N) : "memory");
}

// ---------------------------------------------------------------------------
// Fused pre-pass: z=0..2 cvt q/k/v; z=3..4 cvt weights; z=5 mask bit-pack
// ---------------------------------------------------------------------------

__global__ void prepass_kernel(const float* __restrict__ q,
                               const float* __restrict__ k,
                               const float* __restrict__ v,
                               const float* __restrict__ wq,
                               const float* __restrict__ wo,
                               const int* __restrict__ mask)
{
    const int z = blockIdx.z;
    if (z < 3) {
        const float* in = (z == 0) ? q : (z == 1) ? k : v;
        __half* out = (z == 0) ? g_qh : (z == 1) ? g_kh : g_vh;
        int i = (blockIdx.x * blockDim.x + threadIdx.x) * 8;
        float4 f0 = *(const float4*)&in[i];
        float4 f1 = *(const float4*)&in[i + 4];
        uint2 a = pack4(f0), b = pack4(f1);
        *(uint4*)&out[i] = make_uint4(a.x, a.y, b.x, b.y);
    } else if (z < 5) {
        if (blockIdx.x >= (D * D) / 2048) return;
        const float* in = (z == 3) ? wq : wo;
        __half* out = (z == 3) ? g_wq : g_wo;
        int i = (blockIdx.x * blockDim.x + threadIdx.x) * 8;
        float4 f0 = *(const float4*)&in[i];
        float4 f1 = *(const float4*)&in[i + 4];
        uint2 a = pack4(f0), b = pack4(f1);
        *(uint4*)&out[i] = make_uint4(a.x, a.y, b.x, b.y);
    } else {
        int w = blockIdx.x * blockDim.x + threadIdx.x;
        if (w >= S * S / 32) return;
        const int* p = mask + (size_t)w * 32;
        uint32_t bits = 0;
        #pragma unroll
        for (int i = 0; i < 32; i += 4) {
            int4 m = *(const int4*)&p[i];
            bits |= (m.x != 0 ? 1u : 0u) << i;
            bits |= (m.y != 0 ? 1u : 0u) << (i + 1);
            bits |= (m.z != 0 ? 1u : 0u) << (i + 2);
            bits |= (m.w != 0 ? 1u : 0u) << (i + 3);
        }
        g_Mb[w] = bits;
    }
}

// ---------------------------------------------------------------------------
// proj_qkv (f16 mma + ldmatrix, 3-stage cp.async):
// out[m,n] = sum_k A[m,k] * W[n,k].  Block 128x64, BK=64, 8 warps, warp 32x32.
// Dynamic smem: 3 x (128+64) x 72 halves = 82944 B.
// ---------------------------------------------------------------------------

constexpr int QKV_SMEM = 3 * (128 + 64) * 72 * 2;

__global__ __launch_bounds__(256) void proj_qkv_kernel()
{
    extern __shared__ __half dsm[];
    const int z = blockIdx.z;
    const __half* A = (z == 0) ? g_qh : (z == 1) ? g_kh : g_vh;
    const __half* W = g_wq;

    const int tid  = threadIdx.x;
    const int lane = tid & 31;
    const int warp = tid >> 5;
    const int g = lane >> 2;
    const int t = lane & 3;
    const int wm = warp >> 1;       // 0..3
    const int wn = warp & 1;        // 0..1
    const int m0 = blockIdx.y * 128;
    const int n0 = blockIdx.x * 64;

    auto As = [&](int buf) { return dsm + buf * (192 * 72); };
    auto Bs = [&](int buf) { return dsm + buf * (192 * 72) + 128 * 72; };

    // ldmatrix per-lane relative byte offsets
    const int gi = lane >> 3, li = lane & 7;
    uint32_t arel[2], brel[2];
    #pragma unroll
    for (int i = 0; i < 2; i++)
        arel[i] = (uint32_t)(((wm * 32 + i * 16 + li + (lane & 8)) * 72
                              + ((lane >> 4) & 1) * 8) * 2);
    #pragma unroll
    for (int j2 = 0; j2 < 2; j2++)
        brel[j2] = (uint32_t)(((wn * 32 + j2 * 16 + ((gi >> 1) & 1) * 8 + li) * 72
                               + (gi & 1) * 8) * 2);

    auto stage = [&](int kt, int buf) {
        __half* as = As(buf);
        __half* bs = Bs(buf);
        #pragma unroll
        for (int q = 0; q < 4; q++) {
            int id = tid + q * 256;         // 0..1023
            int row = id >> 3;              // 0..127
            int seg = (id & 7) * 8;
            cp16(&as[row * 72 + seg], &A[(size_t)(m0 + row) * D + kt + seg]);
        }
        #pragma unroll
        for (int q = 0; q < 2; q++) {
            int id = tid + q * 256;         // 0..511
            int row = id >> 3;              // 0..63
            int seg = (id & 7) * 8;
            cp16(&bs[row * 72 + seg], &W[(size_t)(n0 + row) * D + kt + seg]);
        }
        cp_commit();
    };

    stage(0, 0);
    stage(64, 1);

    float4 c[2][4] = {};

    for (int kt = 0; kt < D; kt += 64) {
        const int cb = (kt >> 6) % 3;
        if (kt + 64 < D) cp_wait<1>(); else cp_wait<0>();   // tail drain!
        __syncthreads();
        if (kt + 128 < D) stage(kt + 128, (cb + 2) % 3);

        const uint32_t ab = smem_u32(As(cb));
        const uint32_t bb = smem_u32(Bs(cb));
        #pragma unroll
        for (int ks = 0; ks < 4; ks++) {
            const uint32_t kby = ks * 32;    // k0 * 2 bytes
            uint32_t a[2][4], b[2][4];
            ldsm4(a[0][0], a[0][1], a[0][2], a[0][3], ab + arel[0] + kby);
            ldsm4(a[1][0], a[1][1], a[1][2], a[1][3], ab + arel[1] + kby);
            ldsm4(b[0][0], b[0][1], b[0][2], b[0][3], bb + brel[0] + kby);
            ldsm4(b[1][0], b[1][1], b[1][2], b[1][3], bb + brel[1] + kby);
            #pragma unroll
            for (int j2 = 0; j2 < 2; j2++)
                #pragma unroll
                for (int jj = 0; jj < 2; jj++)
                    #pragma unroll
                    for (int i = 0; i < 2; i++)
                        mma_f16(c[i][j2 * 2 + jj],
                                a[i][0], a[i][1], a[i][2], a[i][3],
                                b[j2][jj * 2], b[j2][jj * 2 + 1]);
        }
        __syncthreads();
    }

    const int h = n0 >> 6;
    if (z != 2) {
        __half* out = (z == 0) ? g_Q : g_K;
        const float scl = (z == 0) ? 0.125f : 1.0f;
        #pragma unroll
        for (int i = 0; i < 2; i++) {
            int r0 = m0 + wm * 32 + i * 16 + g;
            int r1 = r0 + 8;
            int b0i = r0 >> 11, s0 = r0 & 2047;
            int b1i = r1 >> 11, s1 = r1 & 2047;
            #pragma unroll
            for (int j = 0; j < 4; j++) {
                int dk = wn * 32 + j * 8 + 2 * t;
                *(uint32_t*)&out[(((size_t)(b0i * H + h) * S) + s0) * DK + dk] =
                    pack2(c[i][j].x * scl, c[i][j].y * scl);
                *(uint32_t*)&out[(((size_t)(b1i * H + h) * S) + s1) * DK + dk] =
                    pack2(c[i][j].z * scl, c[i][j].w * scl);
            }
        }
    } else {
        // V: transpose via smem, then coalesced writes to [B,H,DK,S]
        __half* Ts = dsm;                   // scratch 64 x 136 halves
        #pragma unroll
        for (int i = 0; i < 2; i++) {
            int rl0 = wm * 32 + i * 16 + g;
            int rl1 = rl0 + 8;
            #pragma unroll
            for (int j = 0; j < 4; j++) {
                int dk = wn * 32 + j * 8 + 2 * t;
                Ts[(dk    ) * 136 + rl0] = __float2half_rn(c[i][j].x);
                Ts[(dk + 1) * 136 + rl0] = __float2half_rn(c[i][j].y);
                Ts[(dk    ) * 136 + rl1] = __float2half_rn(c[i][j].z);
                Ts[(dk + 1) * 136 + rl1] = __float2half_rn(c[i][j].w);
            }
        }
        __syncthreads();
        const int bb2 = m0 >> 11;
        const int sbase = m0 & 2047;
        int row = tid >> 2;                 // dv 0..63
        int seg = (tid & 3) * 32;
        size_t dst = ((size_t)(bb2 * H + h) * DK + row) * S + sbase + seg;
        #pragma unroll
        for (int u = 0; u < 4; u++)
            *(uint4*)&g_V[dst + u * 8] = *(uint4*)&Ts[row * 136 + seg + u * 8];
    }
}

// ---------------------------------------------------------------------------
// proj_out (f16 mma + ldmatrix, 3-stage cp.async):
// Block 64x64, BK=64, 4 warps (2m x 2n), warp 32x32, 128 threads.
// Dynamic smem: 3 x (64+64) x 72 halves = 55296 B.
// ---------------------------------------------------------------------------

constexpr int OUT_SMEM = 3 * 128 * 72 * 2;

__global__ __launch_bounds__(128) void proj_out_kernel(float* __restrict__ out)
{
    extern __shared__ __half dsm[];

    const int tid  = threadIdx.x;
    const int lane = tid & 31;
    const int warp = tid >> 5;      // 0..3
    const int g = lane >> 2;
    const int t = lane & 3;
    const int wm = warp >> 1;       // 0..1
    const int wn = warp & 1;        // 0..1
    const int m0 = blockIdx.y * 64;
    const int n0 = blockIdx.x * 64;

    auto As = [&](int buf) { return dsm + buf * (128 * 72); };
    auto Bs = [&](int buf) { return dsm + buf * (128 * 72) + 64 * 72; };

    const int gi = lane >> 3, li = lane & 7;
    uint32_t arel[2], brel[2];
    #pragma unroll
    for (int i = 0; i < 2; i++)
        arel[i] = (uint32_t)(((wm * 32 + i * 16 + li + (lane & 8)) * 72
                              + ((lane >> 4) & 1) * 8) * 2);
    #pragma unroll
    for (int j2 = 0; j2 < 2; j2++)
        brel[j2] = (uint32_t)(((wn * 32 + j2 * 16 + ((gi >> 1) & 1) * 8 + li) * 72
                               + (gi & 1) * 8) * 2);

    auto stage = [&](int kt, int buf) {
        __half* as = As(buf);
        __half* bs = Bs(buf);
        #pragma unroll
        for (int q = 0; q < 4; q++) {
            int id = tid + q * 128;         // 0..511
            int row = id >> 3;              // 0..63
            int seg = (id & 7) * 8;
            cp16(&as[row * 72 + seg], &g_X[(size_t)(m0 + row) * D + kt + seg]);
            cp16(&bs[row * 72 + seg], &g_wo[(size_t)(n0 + row) * D + kt + seg]);
        }
        cp_commit();
    };

    stage(0, 0);
    stage(64, 1);

    float4 c[2][4] = {};

    for (int kt = 0; kt < D; kt += 64) {
        const int cb = (kt >> 6) % 3;
        if (kt + 64 < D) cp_wait<1>(); else cp_wait<0>();   // tail drain!
        __syncthreads();
        if (kt + 128 < D) stage(kt + 128, (cb + 2) % 3);

        const uint32_t ab = smem_u32(As(cb));
        const uint32_t bb = smem_u32(Bs(cb));
        #pragma unroll
        for (int ks = 0; ks < 4; ks++) {
            const uint32_t kby = ks * 32;
            uint32_t a[2][4], b[2][4];
            ldsm4(a[0][0], a[0][1], a[0][2], a[0][3], ab + arel[0] + kby);
            ldsm4(a[1][0], a[1][1], a[1][2], a[1][3], ab + arel[1] + kby);
            ldsm4(b[0][0], b[0][1], b[0][2], b[0][3], bb + brel[0] + kby);
            ldsm4(b[1][0], b[1][1], b[1][2], b[1][3], bb + brel[1] + kby);
            #pragma unroll
            for (int j2 = 0; j2 < 2; j2++)
                #pragma unroll
                for (int jj = 0; jj < 2; jj++)
                    #pragma unroll
                    for (int i = 0; i < 2; i++)
                        mma_f16(c[i][j2 * 2 + jj],
                                a[i][0], a[i][1], a[i][2], a[i][3],
                                b[j2][jj * 2], b[j2][jj * 2 + 1]);
        }
        __syncthreads();
    }

    #pragma unroll
    for (int i = 0; i < 2; i++) {
        int r0 = m0 + wm * 32 + i * 16 + g;
        int r1 = r0 + 8;
        #pragma unroll
        for (int j = 0; j < 4; j++) {
            int n = n0 + wn * 32 + j * 8 + 2 * t;
            *(float2*)&out[(size_t)r0 * D + n] = make_float2(c[i][j].x, c[i][j].y);
            *(float2*)&out[(size_t)r1 * D + n] = make_float2(c[i][j].z, c[i][j].w);
        }
    }
}

// ---------------------------------------------------------------------------
// Attention (f16 mma + ldmatrix, register-resident P, 3-stage cp.async):
// 64 q-rows/CTA, 8 warps; warp (wm,wn) = 16 rows x 32 score-cols.
// Fixed-base softmax exp(s-4); one barrier per chunk; warp-pair partials
// merged once at the end. mask==0 -> score := 1e-9 (pre-softmax, NOT -inf).
// Dynamic smem: 3 x 2 x 64 x 72 halves + 256 = 55552 B.
// ---------------------------------------------------------------------------

constexpr int KVBUF = 64 * 72;                       // halves per tensor stage
constexpr int ATT_SMEM = (3 * 2 * KVBUF) * 2 + 256;  // bytes

__global__ __launch_bounds__(256, 2) void attn_kernel()
{
    extern __shared__ __half dsm[];
    __half* Ks = dsm;                    // [3][KVBUF] keys x dk
    __half* Vt = dsm + 3 * KVBUF;        // [3][KVBUF] dv x keys
    float* xch = (float*)(dsm + 6 * KVBUF);

    const int q0 = blockIdx.x * 64;
    const int bh = blockIdx.y;
    const __half* Qp = g_Q + (size_t)bh * S * DK;
    const __half* Kp = g_K + (size_t)bh * S * DK;
    const __half* Vg = g_V + (size_t)bh * DK * S;

    const int tid  = threadIdx.x;
    const int lane = tid & 31;
    const int warp = tid >> 5;
    const int g = lane >> 2;
    const int t = lane & 3;
    const int wm = warp >> 1;       // 0..3 -> rows wm*16..+15
    const int wn = warp & 1;        // 0..1 -> score cols wn*32..+31
    const int rw0 = wm * 16 + g;
    const int rw1 = rw0 + 8;
    const int gq0 = q0 + rw0;
    const int gq1 = q0 + rw1;
    const int colb = wn * 32;

    const int srow = tid >> 3;          // 0..31 (x2 iters)
    const int sseg = (tid & 7) * 8;

    // ldmatrix per-lane relative byte offsets
    const int gi = lane >> 3, li = lane & 7;
    uint32_t krel[2], vrel[4];
    #pragma unroll
    for (int j2 = 0; j2 < 2; j2++)
        krel[j2] = (uint32_t)(((colb + j2 * 16 + ((gi >> 1) & 1) * 8 + li) * 72
                               + (gi & 1) * 8) * 2);
    #pragma unroll
    for (int j2 = 0; j2 < 4; j2++)
        vrel[j2] = (uint32_t)(((j2 * 16 + ((gi >> 1) & 1) * 8 + li) * 72
                               + (gi & 1) * 8) * 2);

    // ---- Q fragments straight from gmem (one-time) ----
    uint32_t qa[4][4];
    #pragma unroll
    for (int ks = 0; ks < 4; ks++) {
        const int k0 = ks * 16;
        qa[ks][0] = *(const uint32_t*)&Qp[(size_t)gq0 * DK + k0 + 2 * t    ];
        qa[ks][1] = *(const uint32_t*)&Qp[(size_t)gq1 * DK + k0 + 2 * t    ];
        qa[ks][2] = *(const uint32_t*)&Qp[(size_t)gq0 * DK + k0 + 2 * t + 8];
        qa[ks][3] = *(const uint32_t*)&Qp[(size_t)gq1 * DK + k0 + 2 * t + 8];
    }

    auto stageKV = [&](int k0, int buf) {
        #pragma unroll
        for (int q = 0; q < 2; q++) {
            int row = srow + q * 32;        // key for K, dv for Vt
            cp16(&Ks[buf * KVBUF + row * 72 + sseg],
                 &Kp[(size_t)(k0 + row) * DK + sseg]);
            cp16(&Vt[buf * KVBUF + row * 72 + sseg],
                 &Vg[(size_t)row * S + k0 + sseg]);
        }
        cp_commit();
    };

    stageKV(0, 0);
    stageKV(64, 1);

    float4 o[8] = {};                   // partial O: 16 rows x 64 dv (own keys)
    float rsum0 = 0.f, rsum1 = 0.f;     // partial over this warp's 32 cols

    const uint32_t ksb = smem_u32(Ks);
    const uint32_t vtb = smem_u32(Vt);

    constexpr int NCHUNK = S / 64;
    for (int ci = 0; ci < NCHUNK; ci++) {
        const int cb = ci % 3;
        if (ci + 1 < NCHUNK) cp_wait<1>(); else cp_wait<0>();   // tail drain!
        __syncthreads();                // chunk ci staged; (ci-1) reads done
        if (ci + 2 < NCHUNK) stageKV((ci + 2) * 64, (ci + 2) % 3);

        const uint32_t kcb = ksb + cb * (KVBUF * 2);
        const uint32_t vcb = vtb + cb * (KVBUF * 2);
        const int k0 = ci * 64;

        // mask words for this warp's 32-col span (1 word per row)
        uint32_t mw0 = g_Mb[(size_t)gq0 * (S / 32) + (k0 >> 5) + wn];
        uint32_t mw1 = g_Mb[(size_t)gq1 * (S / 32) + (k0 >> 5) + wn];

        // ---- scores: 16 rows x 32 cols (Q pre-scaled by 1/8) ----
        float4 sc[4] = {};
        #pragma unroll
        for (int ks = 0; ks < 4; ks++) {
            const uint32_t kby = ks * 32;
            uint32_t b[2][4];
            ldsm4(b[0][0], b[0][1], b[0][2], b[0][3], kcb + krel[0] + kby);
            ldsm4(b[1][0], b[1][1], b[1][2], b[1][3], kcb + krel[1] + kby);
            #pragma unroll
            for (int j2 = 0; j2 < 2; j2++)
                #pragma unroll
                for (int jj = 0; jj < 2; jj++)
                    mma_f16(sc[j2 * 2 + jj],
                            qa[ks][0], qa[ks][1], qa[ks][2], qa[ks][3],
                            b[j2][jj * 2], b[j2][jj * 2 + 1]);
        }

        // ---- mask select + fixed-base exp: P = exp(s - 4) ----
        uint32_t pa[2][4];              // P as PV A-fragments (registers only)
        #pragma unroll
        for (int kb = 0; kb < 2; kb++) {
            #pragma unroll
            for (int jj = 0; jj < 2; jj++) {
                int j = kb * 2 + jj;
                int sh = j * 8 + 2 * t;
                float e0 = __expf(((mw0 >> sh)       & 1 ? sc[j].x : 1e-9f) - 4.f);
                float e1 = __expf(((mw0 >> (sh + 1)) & 1 ? sc[j].y : 1e-9f) - 4.f);
                float e2 = __expf(((mw1 >> sh)       & 1 ? sc[j].z : 1e-9f) - 4.f);
                float e3 = __expf(((mw1 >> (sh + 1)) & 1 ? sc[j].w : 1e-9f) - 4.f);
                rsum0 += e0 + e1;
                rsum1 += e2 + e3;
                pa[kb][jj * 2    ] = pack2(e0, e1);   // a0/a2: row g
                pa[kb][jj * 2 + 1] = pack2(e2, e3);   // a1/a3: row g+8
            }
        }

        // ---- O += P[:, own 32 keys] @ V[own 32 keys, 0..63] ----
        #pragma unroll
        for (int kb = 0; kb < 2; kb++) {
            const uint32_t koff = (colb + kb * 16) * 2;
            #pragma unroll
            for (int j2 = 0; j2 < 4; j2++) {
                uint32_t vb[4];
                ldsm4(vb[0], vb[1], vb[2], vb[3], vcb + vrel[j2] + koff);
                mma_f16(o[j2 * 2    ], pa[kb][0], pa[kb][1], pa[kb][2], pa[kb][3],
                        vb[0], vb[1]);
                mma_f16(o[j2 * 2 + 1], pa[kb][0], pa[kb][1], pa[kb][2], pa[kb][3],
                        vb[2], vb[3]);
            }
        }
    }

    // ---- merge warp-pair partials, normalize, write fp16 ----
    rsum0 += __shfl_xor_sync(0xffffffffu, rsum0, 1);
    rsum0 += __shfl_xor_sync(0xffffffffu, rsum0, 2);
    rsum1 += __shfl_xor_sync(0xffffffffu, rsum1, 1);
    rsum1 += __shfl_xor_sync(0xffffffffu, rsum1, 2);

    __syncthreads();                    // KV buffers free for reuse
    float* Osh = (float*)dsm;           // 64 rows x 68 floats (17408 B)
    if (wn == 1) {
        #pragma unroll
        for (int j = 0; j < 8; j++) {
            int cl = j * 8 + 2 * t;
            *(float2*)&Osh[rw0 * 68 + cl] = make_float2(o[j].x, o[j].y);
            *(float2*)&Osh[rw1 * 68 + cl] = make_float2(o[j].z, o[j].w);
        }
        if (t == 0) { xch[rw0] = rsum0; xch[rw1] = rsum1; }
    }
    __syncthreads();
    if (wn == 0) {
        const float inv0 = 1.f / (rsum0 + xch[rw0]);
        const float inv1 = 1.f / (rsum1 + xch[rw1]);
        const int b = bh >> 3;
        const int h = bh & 7;
        #pragma unroll
        for (int j = 0; j < 8; j++) {
            int cl = j * 8 + 2 * t;
            float2 e0 = *(float2*)&Osh[rw0 * 68 + cl];
            float2 e1 = *(float2*)&Osh[rw1 * 68 + cl];
            *(uint32_t*)&g_X[((size_t)(b * S + gq0)) * D + h * 64 + cl] =
                pack2((o[j].x + e0.x) * inv0, (o[j].y + e0.y) * inv0);
            *(uint32_t*)&g_X[((size_t)(b * S + gq1)) * D + h * 64 + cl] =
                pack2((o[j].z + e1.x) * inv1, (o[j].w + e1.y) * inv1);
        }
    }
}

// ---------------------------------------------------------------------------

extern "C" void kernel_launch(void* const* d_in, const int* in_sizes, int n_in,
                              void* d_out, int out_size)
{
    const float* q    = (const float*)d_in[0];
    const float* k    = (const float*)d_in[1];
    const float* v    = (const float*)d_in[2];
    const int*   mask = (const int*)d_in[3];
    const float* Wq   = (const float*)d_in[4];
    const float* Wo   = (const float*)d_in[5];
    float* out = (float*)d_out;

    cudaFuncSetAttribute(proj_qkv_kernel,
                         cudaFuncAttributeMaxDynamicSharedMemorySize, QKV_SMEM);
    cudaFuncSetAttribute(proj_out_kernel,
                         cudaFuncAttributeMaxDynamicSharedMemorySize, OUT_SMEM);
    cudaFuncSetAttribute(attn_kernel,
                         cudaFuncAttributeMaxDynamicSharedMemorySize, ATT_SMEM);

    prepass_kernel<<<dim3((B * S * D) / 2048, 1, 6), 256>>>(q, k, v, Wq, Wo, mask);

    proj_qkv_kernel<<<dim3(D / 64, (B * S) / 128, 3), 256, QKV_SMEM>>>();
    attn_kernel<<<dim3(S / 64, B * H), 256, ATT_SMEM>>>();
    proj_out_kernel<<<dim3(D / 64, (B * S) / 64), 128, OUT_SMEM>>>(out);
}